// round 14
// baseline (speedup 1.0000x reference)
#include <cuda_runtime.h>
#include <cuda_bf16.h>

#define LF   256
#define LS   128
#define NC   8
#define NN   512
#define PL   (NC*LF*NN)      // 1,048,576  (c,t,n) sites

// scratch (plane-major; consumers' warp lanes = consecutive n => coalesced)
__device__ __align__(16) float  g_scp[16*PL];   // sc per di-plane
__device__ __align__(16) float2 g_misc[PL];     // {dtlo, xv3}
__device__ __align__(16) float4 g_B4[4*PL];     // B quads per q-plane
__device__ __align__(16) float4 g_C4[4*PL];     // C quads per q-plane
__device__ __align__(16) float  g_yf[16*PL];    // gated y per di-plane
__device__ __align__(16) float  g_part[NC*16*NN*8];

__device__ __forceinline__ float fsig(float x) {
    float e = __expf(-fabsf(x));
    float r = __frcp_rn(1.0f + e);
    return (x >= 0.0f) ? r : e * r;
}
__device__ __forceinline__ float fsilu(float x) { return x * fsig(x); }
__device__ __forceinline__ float dot16s(const float* sc, const float* w) {
    float r = sc[0] * w[0];
    #pragma unroll
    for (int i = 1; i < 16; ++i) r = fmaf(sc[i], w[i], r);
    return r;
}

// ========== Kernel A: folded lift+in_proj + conv + silu + x_proj ==========
__global__ void __launch_bounds__(256) kA(
    const float* __restrict__ x,     const float* __restrict__ lift_w,
    const float* __restrict__ lift_b,const float* __restrict__ ipw,
    const float* __restrict__ conv_w,const float* __restrict__ conv_b,
    const float* __restrict__ xpw)
{
    __shared__ float s_xpw[528];
    __shared__ float s_w1[16], s_b1[16], s_cw[64], s_cb[16];

    const int tid = threadIdx.x, t = blockIdx.x, c = blockIdx.y;

    for (int i = tid; i < 528; i += 256) s_xpw[i] = xpw[c*528 + i];
    if (tid < 16) {
        float w = 0.f, bs = 0.f;
        #pragma unroll
        for (int d = 0; d < 8; ++d) {
            float ip = ipw[(c*32 + tid)*8 + d];
            w  = fmaf(lift_w[c*8 + d], ip, w);
            bs = fmaf(lift_b[c*8 + d], ip, bs);
        }
        s_w1[tid] = w; s_b1[tid] = bs;
    } else if (tid < 80) s_cw[tid-16] = conv_w[c*64 + (tid-16)];
    else if (tid < 96)   s_cb[tid-80] = conv_b[c*16 + (tid-80)];
    __syncthreads();

    const float m0 = (t >= 3) ? 1.f : 0.f;
    const float m1 = (t >= 2) ? 1.f : 0.f;
    const float m2 = (t >= 1) ? 1.f : 0.f;

    #pragma unroll
    for (int half = 0; half < 2; ++half) {
        const int n = tid + half*256;
        const int b = n >> 7, ls = n & 127;
        const float* xb = x + ((size_t)b*LF*LS + ls)*NC + c;
        const float xv0 = (t >= 3) ? __ldg(xb + (size_t)(t-3)*(LS*NC)) : 0.f;
        const float xv1 = (t >= 2) ? __ldg(xb + (size_t)(t-2)*(LS*NC)) : 0.f;
        const float xv2 = (t >= 1) ? __ldg(xb + (size_t)(t-1)*(LS*NC)) : 0.f;
        const float xv3 =            __ldg(xb + (size_t)t*(LS*NC));

        float sc[16];
        #pragma unroll
        for (int di = 0; di < 16; ++di) {
            float w = s_w1[di], bs = s_b1[di];
            float acc = s_cb[di];
            acc = fmaf(m0 * fmaf(xv0, w, bs), s_cw[di*4+0], acc);
            acc = fmaf(m1 * fmaf(xv1, w, bs), s_cw[di*4+1], acc);
            acc = fmaf(m2 * fmaf(xv2, w, bs), s_cw[di*4+2], acc);
            acc = fmaf(     fmaf(xv3, w, bs), s_cw[di*4+3], acc);
            sc[di] = fsilu(acc);
        }

        const int ctn = (c*LF + t)*NN + n;
        #pragma unroll
        for (int di = 0; di < 16; ++di) g_scp[di*PL + ctn] = sc[di];

        const float dtlo = dot16s(sc, s_xpw);
        g_misc[ctn] = make_float2(dtlo, xv3);

        #pragma unroll
        for (int q = 0; q < 4; ++q) {
            float v0 = dot16s(sc, s_xpw + (1 + 4*q + 0)*16);
            float v1 = dot16s(sc, s_xpw + (1 + 4*q + 1)*16);
            float v2 = dot16s(sc, s_xpw + (1 + 4*q + 2)*16);
            float v3 = dot16s(sc, s_xpw + (1 + 4*q + 3)*16);
            g_B4[q*PL + ctn] = make_float4(v0, v1, v2, v3);
        }
        #pragma unroll
        for (int q = 0; q < 4; ++q) {
            float v0 = dot16s(sc, s_xpw + (17 + 4*q + 0)*16);
            float v1 = dot16s(sc, s_xpw + (17 + 4*q + 1)*16);
            float v2 = dot16s(sc, s_xpw + (17 + 4*q + 2)*16);
            float v3 = dot16s(sc, s_xpw + (17 + 4*q + 3)*16);
            g_C4[q*PL + ctn] = make_float4(v0, v1, v2, v3);
        }
    }
}

// ========== Kernel B: barrier-free scan; direct LDG + depth-1 prefetch ==========
// block = (c, 32-n tile); 8 warps free-running, warp w owns di {2w, 2w+1}; lanes = n.
// All 8 warps load the same per-step 6.4KB: first touch fills L1, rest hit L1.
__global__ void __launch_bounds__(256, 1) kB(
    const float* __restrict__ A_log,  const float* __restrict__ D_skip,
    const float* __restrict__ dt_w,   const float* __restrict__ dt_b,
    const float* __restrict__ lift_w, const float* __restrict__ lift_b,
    const float* __restrict__ ipw)
{
    const int tid  = threadIdx.x;
    const int w    = tid >> 5, lane = tid & 31;
    const int c    = blockIdx.x >> 4;
    const int n    = (blockIdx.x & 15)*32 + lane;
    const int di0  = 2*w, di1 = di0 + 1;
    const int base = c*LF*NN + n;             // + t*NN per step

    // per-warp constants
    const float dtw0 = __ldg(&dt_w[c*16+di0]), dtw1 = __ldg(&dt_w[c*16+di1]);
    const float dtb0 = __ldg(&dt_b[c*16+di0]), dtb1 = __ldg(&dt_b[c*16+di1]);
    const float Dsk0 = __ldg(&D_skip[c*16+di0]), Dsk1 = __ldg(&D_skip[c*16+di1]);
    float w1z0 = 0.f, b1z0 = 0.f, w1z1 = 0.f, b1z1 = 0.f;
    #pragma unroll
    for (int d = 0; d < 8; ++d) {
        float lw = __ldg(&lift_w[c*8+d]), lb = __ldg(&lift_b[c*8+d]);
        float ip0 = __ldg(&ipw[(c*32 + 16 + di0)*8 + d]);
        float ip1 = __ldg(&ipw[(c*32 + 16 + di1)*8 + d]);
        w1z0 = fmaf(lw, ip0, w1z0); b1z0 = fmaf(lb, ip0, b1z0);
        w1z1 = fmaf(lw, ip1, w1z1); b1z1 = fmaf(lb, ip1, b1z1);
    }
    bool stl = true;
    #pragma unroll
    for (int s = 0; s < 16; ++s) {
        float a0 = -__expf(__ldg(&A_log[(c*16+di0)*16 + s]));
        float a1 = -__expf(__ldg(&A_log[(c*16+di1)*16 + s]));
        stl = stl && (fabsf(a0 + (float)(s+1)) <= 1e-4f*(s+1))
                  && (fabsf(a1 + (float)(s+1)) <= 1e-4f*(s+1));
    }
    const bool st = __all_sync(0xffffffffu, stl);

    float h0[16], h1[16];
    #pragma unroll
    for (int s = 0; s < 16; ++s) { h0[s] = 0.f; h1[s] = 0.f; }

    const float* SC0 = g_scp + di0*PL;
    const float* SC1 = g_scp + di1*PL;
    float* Y0 = g_yf + di0*PL + base;
    float* Y1 = g_yf + di1*PL + base;

    // prefetch t=0
    float4 nB0 = __ldg(&g_B4[0*PL + base]), nB1 = __ldg(&g_B4[1*PL + base]);
    float4 nB2 = __ldg(&g_B4[2*PL + base]), nB3 = __ldg(&g_B4[3*PL + base]);
    float4 nC0 = __ldg(&g_C4[0*PL + base]), nC1 = __ldg(&g_C4[1*PL + base]);
    float4 nC2 = __ldg(&g_C4[2*PL + base]), nC3 = __ldg(&g_C4[3*PL + base]);
    float  ns0 = __ldg(&SC0[base]), ns1 = __ldg(&SC1[base]);
    float2 nms = __ldg(&g_misc[base]);

    if (st) {
        for (int t = 0; t < LF; ++t) {
            float4 B0=nB0, B1=nB1, B2=nB2, B3=nB3;
            float4 C0=nC0, C1=nC1, C2=nC2, C3=nC3;
            float sc0=ns0, sc1=ns1;
            float2 ms=nms;
            if (t + 1 < LF) {
                const int cn = base + (t+1)*NN;
                nB0 = __ldg(&g_B4[0*PL + cn]); nB1 = __ldg(&g_B4[1*PL + cn]);
                nB2 = __ldg(&g_B4[2*PL + cn]); nB3 = __ldg(&g_B4[3*PL + cn]);
                nC0 = __ldg(&g_C4[0*PL + cn]); nC1 = __ldg(&g_C4[1*PL + cn]);
                nC2 = __ldg(&g_C4[2*PL + cn]); nC3 = __ldg(&g_C4[3*PL + cn]);
                ns0 = __ldg(&SC0[cn]); ns1 = __ldg(&SC1[cn]);
                nms = __ldg(&g_misc[cn]);
            }

            float v0 = fmaf(ms.x, dtw0, dtb0);
            float e0 = __expf(-fabsf(v0));
            float r0 = __frcp_rn(1.0f + e0);
            float dt0 = fmaxf(v0, 0.f) + __logf(1.0f + e0);
            float e1_0 = (v0 >= 0.f) ? e0*r0 : r0;
            float zg0 = fsilu(fmaf(ms.y, w1z0, b1z0));
            float u0  = dt0 * sc0;

            float v1 = fmaf(ms.x, dtw1, dtb1);
            float e1x = __expf(-fabsf(v1));
            float r1 = __frcp_rn(1.0f + e1x);
            float dt1 = fmaxf(v1, 0.f) + __logf(1.0f + e1x);
            float e1_1 = (v1 >= 0.f) ? e1x*r1 : r1;
            float zg1 = fsilu(fmaf(ms.y, w1z1, b1z1));
            float u1  = dt1 * sc1;

            float y0, y1;
            {
                float p1=e1_0, p2=p1*p1, p3=p2*p1, p4=p2*p2;
                float p5=p4*p1, p6=p4*p2, p7=p4*p3, p8=p4*p4;
                float p9=p8*p1, p10=p8*p2, p11=p8*p3, p12=p8*p4;
                float p13=p8*p5, p14=p8*p6, p15=p8*p7, p16=p8*p8;
                h0[0]=fmaf(p1,h0[0],u0*B0.x);   h0[1]=fmaf(p2,h0[1],u0*B0.y);
                h0[2]=fmaf(p3,h0[2],u0*B0.z);   h0[3]=fmaf(p4,h0[3],u0*B0.w);
                h0[4]=fmaf(p5,h0[4],u0*B1.x);   h0[5]=fmaf(p6,h0[5],u0*B1.y);
                h0[6]=fmaf(p7,h0[6],u0*B1.z);   h0[7]=fmaf(p8,h0[7],u0*B1.w);
                h0[8]=fmaf(p9,h0[8],u0*B2.x);   h0[9]=fmaf(p10,h0[9],u0*B2.y);
                h0[10]=fmaf(p11,h0[10],u0*B2.z);h0[11]=fmaf(p12,h0[11],u0*B2.w);
                h0[12]=fmaf(p13,h0[12],u0*B3.x);h0[13]=fmaf(p14,h0[13],u0*B3.y);
                h0[14]=fmaf(p15,h0[14],u0*B3.z);h0[15]=fmaf(p16,h0[15],u0*B3.w);
                y0 = h0[0]*C0.x;
                y0=fmaf(h0[1],C0.y,y0);  y0=fmaf(h0[2],C0.z,y0);  y0=fmaf(h0[3],C0.w,y0);
                y0=fmaf(h0[4],C1.x,y0);  y0=fmaf(h0[5],C1.y,y0);  y0=fmaf(h0[6],C1.z,y0);
                y0=fmaf(h0[7],C1.w,y0);  y0=fmaf(h0[8],C2.x,y0);  y0=fmaf(h0[9],C2.y,y0);
                y0=fmaf(h0[10],C2.z,y0); y0=fmaf(h0[11],C2.w,y0); y0=fmaf(h0[12],C3.x,y0);
                y0=fmaf(h0[13],C3.y,y0); y0=fmaf(h0[14],C3.z,y0); y0=fmaf(h0[15],C3.w,y0);
            }
            {
                float p1=e1_1, p2=p1*p1, p3=p2*p1, p4=p2*p2;
                float p5=p4*p1, p6=p4*p2, p7=p4*p3, p8=p4*p4;
                float p9=p8*p1, p10=p8*p2, p11=p8*p3, p12=p8*p4;
                float p13=p8*p5, p14=p8*p6, p15=p8*p7, p16=p8*p8;
                h1[0]=fmaf(p1,h1[0],u1*B0.x);   h1[1]=fmaf(p2,h1[1],u1*B0.y);
                h1[2]=fmaf(p3,h1[2],u1*B0.z);   h1[3]=fmaf(p4,h1[3],u1*B0.w);
                h1[4]=fmaf(p5,h1[4],u1*B1.x);   h1[5]=fmaf(p6,h1[5],u1*B1.y);
                h1[6]=fmaf(p7,h1[6],u1*B1.z);   h1[7]=fmaf(p8,h1[7],u1*B1.w);
                h1[8]=fmaf(p9,h1[8],u1*B2.x);   h1[9]=fmaf(p10,h1[9],u1*B2.y);
                h1[10]=fmaf(p11,h1[10],u1*B2.z);h1[11]=fmaf(p12,h1[11],u1*B2.w);
                h1[12]=fmaf(p13,h1[12],u1*B3.x);h1[13]=fmaf(p14,h1[13],u1*B3.y);
                h1[14]=fmaf(p15,h1[14],u1*B3.z);h1[15]=fmaf(p16,h1[15],u1*B3.w);
                y1 = h1[0]*C0.x;
                y1=fmaf(h1[1],C0.y,y1);  y1=fmaf(h1[2],C0.z,y1);  y1=fmaf(h1[3],C0.w,y1);
                y1=fmaf(h1[4],C1.x,y1);  y1=fmaf(h1[5],C1.y,y1);  y1=fmaf(h1[6],C1.z,y1);
                y1=fmaf(h1[7],C1.w,y1);  y1=fmaf(h1[8],C2.x,y1);  y1=fmaf(h1[9],C2.y,y1);
                y1=fmaf(h1[10],C2.z,y1); y1=fmaf(h1[11],C2.w,y1); y1=fmaf(h1[12],C3.x,y1);
                y1=fmaf(h1[13],C3.y,y1); y1=fmaf(h1[14],C3.z,y1); y1=fmaf(h1[15],C3.w,y1);
            }

            Y0[t*NN] = fmaf(Dsk0, sc0, y0) * zg0;
            Y1[t*NN] = fmaf(Dsk1, sc1, y1) * zg1;
        }
    } else {
        // generic A path (not taken for this dataset; correctness fallback)
        for (int t = 0; t < LF; ++t) {
            float4 B0=nB0, B1=nB1, B2=nB2, B3=nB3;
            float4 C0=nC0, C1=nC1, C2=nC2, C3=nC3;
            float sc0=ns0, sc1=ns1;
            float2 ms=nms;
            if (t + 1 < LF) {
                const int cn = base + (t+1)*NN;
                nB0 = __ldg(&g_B4[0*PL + cn]); nB1 = __ldg(&g_B4[1*PL + cn]);
                nB2 = __ldg(&g_B4[2*PL + cn]); nB3 = __ldg(&g_B4[3*PL + cn]);
                nC0 = __ldg(&g_C4[0*PL + cn]); nC1 = __ldg(&g_C4[1*PL + cn]);
                nC2 = __ldg(&g_C4[2*PL + cn]); nC3 = __ldg(&g_C4[3*PL + cn]);
                ns0 = __ldg(&SC0[cn]); ns1 = __ldg(&SC1[cn]);
                nms = __ldg(&g_misc[cn]);
            }

            float v0 = fmaf(ms.x, dtw0, dtb0);
            float e0 = __expf(-fabsf(v0));
            float dt0 = fmaxf(v0, 0.f) + __logf(1.0f + e0);
            float zg0 = fsilu(fmaf(ms.y, w1z0, b1z0));
            float u0  = dt0 * sc0;

            float v1 = fmaf(ms.x, dtw1, dtb1);
            float e1x = __expf(-fabsf(v1));
            float dt1 = fmaxf(v1, 0.f) + __logf(1.0f + e1x);
            float zg1 = fsilu(fmaf(ms.y, w1z1, b1z1));
            float u1  = dt1 * sc1;

            float Bv[16] = {B0.x,B0.y,B0.z,B0.w, B1.x,B1.y,B1.z,B1.w,
                            B2.x,B2.y,B2.z,B2.w, B3.x,B3.y,B3.z,B3.w};
            float Cv[16] = {C0.x,C0.y,C0.z,C0.w, C1.x,C1.y,C1.z,C1.w,
                            C2.x,C2.y,C2.z,C2.w, C3.x,C3.y,C3.z,C3.w};
            float y0 = 0.f, y1 = 0.f;
            #pragma unroll
            for (int s = 0; s < 16; ++s) {
                float a0 = -__expf(__ldg(&A_log[(c*16+di0)*16 + s]));
                float a1 = -__expf(__ldg(&A_log[(c*16+di1)*16 + s]));
                h0[s] = fmaf(__expf(dt0*a0), h0[s], u0*Bv[s]);
                h1[s] = fmaf(__expf(dt1*a1), h1[s], u1*Bv[s]);
                y0 = fmaf(h0[s], Cv[s], y0);
                y1 = fmaf(h1[s], Cv[s], y1);
            }

            Y0[t*NN] = fmaf(Dsk0, sc0, y0) * zg0;
            Y1[t*NN] = fmaf(Dsk1, sc1, y1) * zg1;
        }
    }
}

// ========== Kernel C: folded out_proj∘blk + partial time-pooling ==========
__global__ void __launch_bounds__(256) kC(
    const float* __restrict__ out_w, const float* __restrict__ blk_w,
    const float* __restrict__ blk_b)
{
    const int id = blockIdx.x*256 + threadIdx.x;
    const int n = id & 511, chunk = (id >> 9) & 15, c = id >> 13;
    const int tid = threadIdx.x;

    __shared__ float s_M[8][16];
    __shared__ float s_bb[8];
    if (tid < 128) {
        int d = tid >> 4, i = tid & 15;
        float m = 0.f;
        #pragma unroll
        for (int e = 0; e < 8; ++e)
            m = fmaf(blk_w[(c*8+d)*8+e], out_w[(c*8+e)*16+i], m);
        s_M[d][i] = m;
        if (i == 0) s_bb[d] = blk_b[c*8+d];
    }
    __syncthreads();

    float acc[8] = {0,0,0,0,0,0,0,0};
    #pragma unroll 2
    for (int tt = 0; tt < 16; ++tt) {
        const int ctn = (c*LF + chunk*16 + tt)*NN + n;
        float y[16];
        #pragma unroll
        for (int di = 0; di < 16; ++di) y[di] = __ldg(&g_yf[di*PL + ctn]);
        #pragma unroll
        for (int d = 0; d < 8; ++d) {
            float v = s_bb[d];
            #pragma unroll
            for (int i = 0; i < 16; ++i) v = fmaf(y[i], s_M[d][i], v);
            acc[d] += fsilu(v);
        }
    }
    #pragma unroll
    for (int d = 0; d < 8; ++d)
        g_part[((c*16 + chunk)*NN + n)*8 + d] = acc[d];
}

// ========== Kernel D: final pooling + LayerNorm(64) ==========
__global__ void __launch_bounds__(64) kD(
    const float* __restrict__ ln_g, const float* __restrict__ ln_b,
    float* __restrict__ out)
{
    const int n = blockIdx.x, f = threadIdx.x;
    const int c = f >> 3, d = f & 7;
    float s = 0.f;
    #pragma unroll
    for (int ch = 0; ch < 16; ++ch)
        s += g_part[((c*16 + ch)*NN + n)*8 + d];
    float feat = s * (1.0f/256.0f);

    __shared__ float buf[64];
    buf[f] = feat;
    __syncthreads();
    float s1 = 0.f, s2 = 0.f;
    #pragma unroll
    for (int i = 0; i < 64; ++i) { float v = buf[i]; s1 += v; s2 = fmaf(v, v, s2); }
    float mu  = s1 * (1.0f/64.0f);
    float var = fmaxf(s2 * (1.0f/64.0f) - mu*mu, 0.f);
    float inv = rsqrtf(var + 1e-5f);
    out[n*64 + f] = (feat - mu) * inv * ln_g[f] + ln_b[f];
}

extern "C" void kernel_launch(void* const* d_in, const int* in_sizes, int n_in,
                              void* d_out, int out_size) {
    const float* x      = (const float*)d_in[0];
    const float* lift_w = (const float*)d_in[1];
    const float* lift_b = (const float*)d_in[2];
    const float* ipw    = (const float*)d_in[3];
    const float* conv_w = (const float*)d_in[4];
    const float* conv_b = (const float*)d_in[5];
    const float* xpw    = (const float*)d_in[6];
    const float* dt_w   = (const float*)d_in[7];
    const float* dt_b   = (const float*)d_in[8];
    const float* A_log  = (const float*)d_in[9];
    const float* D_skip = (const float*)d_in[10];
    const float* out_w  = (const float*)d_in[11];
    const float* blk_w  = (const float*)d_in[12];
    const float* blk_b  = (const float*)d_in[13];
    const float* ln_g   = (const float*)d_in[14];
    const float* ln_b   = (const float*)d_in[15];
    float* out = (float*)d_out;

    kA<<<dim3(LF, NC), 256>>>(x, lift_w, lift_b, ipw, conv_w, conv_b, xpw);
    kB<<<128, 256>>>(A_log, D_skip, dt_w, dt_b, lift_w, lift_b, ipw);
    kC<<<256, 256>>>(out_w, blk_w, blk_b);
    kD<<<NN, 64>>>(ln_g, ln_b, out);
}